// round 1
// baseline (speedup 1.0000x reference)
#include <cuda_runtime.h>
#include <cstdint>

// Problem constants (fixed by the reference).
#define IMAGE_TOKEN_ID 31999
#define B_DIM 4
#define L_DIM 1024
#define D_DIM 2048
#define NUM_VIS 576
#define NEW_LEN (L_DIM - 1 + NUM_VIS)   // 1599

// Scratch: per-batch image-token position (found from data each call).
__device__ int g_img_pos[B_DIM];

// ---------------------------------------------------------------------------
// Kernel 1: locate the (unique) image token per batch row.
// B*L = 4096 int32 — trivial; exactly one match per row, so no race.
// ---------------------------------------------------------------------------
__global__ void find_img_pos_kernel(const int* __restrict__ input_ids) {
    int idx = blockIdx.x * blockDim.x + threadIdx.x;
    if (idx < B_DIM * L_DIM) {
        if (input_ids[idx] == IMAGE_TOKEN_ID) {
            g_img_pos[idx / L_DIM] = idx % L_DIM;
        }
    }
}

// ---------------------------------------------------------------------------
// Kernel 2: merged-row copy. One block per output row (B*NEW_LEN rows),
// 256 threads, each thread moves 2 x float4 (D=2048 floats = 512 float4).
// Optionally writes position_ids (as float values) after the merged block.
// ---------------------------------------------------------------------------
__global__ __launch_bounds__(256, 8)
void merge_kernel(const int* __restrict__ input_ids,
                  const float4* __restrict__ visual,      // [B, NUM_VIS, D/4]
                  const float4* __restrict__ embed,       // [32768, D/4]
                  float4* __restrict__ out,               // [B, NEW_LEN, D/4]
                  float* __restrict__ out_flat,           // same buffer as float*
                  int write_pos)
{
    const int row = blockIdx.x;                 // 0 .. B*NEW_LEN-1
    const int b = row / NEW_LEN;
    const int j = row - b * NEW_LEN;
    const int ip = g_img_pos[b];

    const float4* src;
    if (j >= ip && j < ip + NUM_VIS) {
        // visual block
        src = visual + ((size_t)b * NUM_VIS + (size_t)(j - ip)) * (D_DIM / 4);
    } else {
        // text token: undo the +NUM_VIS-1 shift after the image position
        const int l = (j < ip) ? j : j - (NUM_VIS - 1);
        const int tok = input_ids[b * L_DIM + l];
        src = embed + (size_t)tok * (D_DIM / 4);
    }

    float4* dst = out + (size_t)row * (D_DIM / 4);
    const int t = threadIdx.x;
    // D/4 = 512 float4 per row; 256 threads -> 2 each. Fully coalesced 128-bit.
    float4 v0 = src[t];
    float4 v1 = src[t + 256];
    dst[t]       = v0;
    dst[t + 256] = v1;

    if (write_pos && t == 0) {
        out_flat[(size_t)B_DIM * NEW_LEN * D_DIM + row] = (float)j;
    }
}

// ---------------------------------------------------------------------------
// Launch contract
// inputs (metadata order): input_ids [B,L] int32, visual_tokens [B,NUM_VIS,D]
// float32, embed_table [32768,D] float32.
// output: merged [B,NEW_LEN,D] float32 (+ optionally position_ids appended).
// ---------------------------------------------------------------------------
extern "C" void kernel_launch(void* const* d_in, const int* in_sizes, int n_in,
                              void* d_out, int out_size)
{
    const int*    input_ids = (const int*)   d_in[0];
    const float4* visual    = (const float4*)d_in[1];
    const float4* embed     = (const float4*)d_in[2];

    float4* out      = (float4*)d_out;
    float*  out_flat = (float*) d_out;

    const long long merged_elems = (long long)B_DIM * NEW_LEN * D_DIM;
    const int write_pos = (out_size > merged_elems) ? 1 : 0;

    find_img_pos_kernel<<<(B_DIM * L_DIM + 255) / 256, 256>>>(input_ids);
    merge_kernel<<<B_DIM * NEW_LEN, 256>>>(input_ids, visual, embed,
                                           out, out_flat, write_pos);
}